// round 9
// baseline (speedup 1.0000x reference)
#include <cuda_runtime.h>
#include <math.h>

#define CC 19
#define DD 128
#define WW 512
#define HWU (512*512)        // 262144
#define HWF (128*128)        // 16384
#define NPIX_F 65536
#define NPIX_U 1048576
#define KD_BLOCKS 512        // (NPIX_F/(128*4))*4 maps

typedef unsigned long long u64;

// ---------------- scratch (device globals; zero at load, self-cleaned) ------
__device__ __align__(16) float g_ru4[NPIX_F*4];
__device__ unsigned char g_pseudo[NPIX_F];
__device__ float         g_sum_l[CC*DD];
__device__ float         g_sum_u[CC*DD];
__device__ float         g_cnt_l[CC];
__device__ float         g_cnt_u[CC];
__device__ float         g_wsum_u[CC];
__device__ float         g_mem[CC*DD];
__device__ __align__(16) u64 g_memdup[DD*20];   // duplicated (m,m) pairs, [d][c]
__device__ int           g_init[CC];
__device__ double        g_ucps;
__device__ double        g_ce[4];
__device__ double        g_cv[4];
__device__ unsigned int  g_done;

// lower half of the bank (c2 = 0..4) via the constant port; upper half via shared.
__constant__ __align__(16) u64 c_bank[DD*20];

__device__ __forceinline__ float warpSum(float v){
#pragma unroll
    for (int o = 16; o; o >>= 1) v += __shfl_down_sync(0xffffffffu, v, o);
    return v;
}
__device__ __forceinline__ void fma2(u64& d, u64 a, u64 b){
    asm("fma.rn.f32x2 %0, %1, %2, %0;" : "+l"(d) : "l"(a), "l"(b));
}
__device__ __forceinline__ float f2lo(u64 x){ return __uint_as_float((unsigned)(x & 0xffffffffu)); }
__device__ __forceinline__ float f2hi(u64 x){ return __uint_as_float((unsigned)(x >> 32)); }
__device__ __forceinline__ u64 fdup(float v){ unsigned u = __float_as_uint(v); return ((u64)u << 32) | u; }

// ===== kernel W: fused [reliability/UCPS]  +  [labeled prototype sums] ======
// Register diet in the kA path: no e1/e2 arrays (exp recomputed in KL pass).
__global__ __launch_bounds__(256) void kW(const float* __restrict__ L1,
                                          const float* __restrict__ L2,
                                          const float* __restrict__ fl1,
                                          const float* __restrict__ fl2,
                                          const int*   __restrict__ gt){
    __shared__ float s_tile[DD*33];
    __shared__ float s_privA[CC*DD];
    __shared__ float s_privB[CC*DD];
    __shared__ float s_cl[CC];
    __shared__ int   s_lab[32];
    __shared__ float sred[8];

    int tid = threadIdx.x;
    unsigned bx = blockIdx.x;

    if ((bx % 9u) == 8u){
        // ------------------- labeled prototype block -------------------
        int grp = bx / 9u;                        // 0..511, 4 tiles each
        for (int i = tid; i < CC*DD; i += 256){ s_privA[i] = 0.f; s_privB[i] = 0.f; }
        if (tid < CC) s_cl[tid] = 0.f;
        __syncthreads();

        int px = tid & 31, dgrp = tid >> 5;
        int d  = tid & 127, half = tid >> 7;
        float* priv = half ? s_privB : s_privA;

#pragma unroll 1
        for (int tt = 0; tt < 4; tt++){
            int p0  = (grp*4 + tt) * 32;
            int b   = p0 >> 14;
            int ij0 = p0 & (HWF-1);
            if (tid < 32){
                int ii = (ij0 + tid) >> 7, jj = (ij0 + tid) & 127;
                int lab = gt[(size_t)b*HWU + (size_t)(ii*4)*WW + (jj*4)];
                s_lab[tid] = lab;
                atomicAdd(&s_cl[lab], 1.f);
            }
            const float* b1 = fl1 + (size_t)b*DD*HWF + ij0 + px;
            const float* b2 = fl2 + (size_t)b*DD*HWF + ij0 + px;
#pragma unroll
            for (int k = 0; k < 16; k++){
                int dd = dgrp*16 + k;
                int o = dd*HWF;
                s_tile[dd*33 + px] = 0.5f*(__ldg(b1 + o) + __ldg(b2 + o));
            }
            __syncthreads();
#pragma unroll
            for (int p = 0; p < 16; p++){
                int pp = half*16 + p;
                int lab = s_lab[pp];
                priv[lab*DD + d] += s_tile[d*33 + pp];
            }
            __syncthreads();
        }
        for (int t = tid; t < CC*DD; t += 256)
            atomicAdd(&g_sum_l[t], s_privA[t] + s_privB[t]);
        if (tid < CC) atomicAdd(&g_cnt_l[tid], s_cl[tid]);
        return;
    }

    // --------------------------- kA block -----------------------------
    int aidx = bx - bx/9u;                        // 0..4095
    int idx = aidx*256 + tid;
    int w = idx & (WW-1);
    int h = (idx >> 9) & 511;
    int b = idx >> 18;
    const float* p1 = L1 + (size_t)b * CC * HWU + (size_t)h * WW + w;
    const float* p2 = L2 + (size_t)b * CC * HWU + (size_t)h * WW + w;

    float l1[CC], l2[CC];
#pragma unroll
    for (int c = 0; c < CC; c++){
        l1[c] = __ldg(p1 + c*HWU);
        l2[c] = __ldg(p2 + c*HWU);
    }
    float m1 = l1[0], m2 = l2[0];
    int y1 = 0, y2 = 0;
#pragma unroll
    for (int c = 1; c < CC; c++){
        if (l1[c] > m1){ m1 = l1[c]; y1 = c; }
        if (l2[c] > m2){ m2 = l2[c]; y2 = c; }
    }
    float s1 = 0.f, s2 = 0.f;
#pragma unroll
    for (int c = 0; c < CC; c++){
        s1 += __expf(l1[c] - m1);
        s2 += __expf(l2[c] - m2);
    }
    float lse1 = m1 + __logf(s1), lse2 = m2 + __logf(s2);
    float i1 = __fdividef(1.f, s1), i2 = __fdividef(1.f, s2);

    const float LOGEPS = -16.118095651f;          // log(1e-7)
    float kl = 0.f;
#pragma unroll
    for (int c = 0; c < CC; c++){
        float t1 = l1[c] - lse1, t2 = l2[c] - lse2;
        float q1 = __expf(t1),   q2 = __expf(t2);
        float logm = __logf(fmaxf(0.5f*(q1+q2), 1e-7f));
        kl += q1 * (fmaxf(t1, LOGEPS) - logm)
            + q2 * (fmaxf(t2, LOGEPS) - logm);
    }
    float conf = 0.5f*(i1 + i2);
    float r_u  = (y1 == y2) ? conf * __expf(-0.5f*kl) : 0.f;

    float l1y2 = 0.f, l2y1 = 0.f;
#pragma unroll
    for (int c = 0; c < CC; c++){
        if (c == y2) l1y2 = l1[c];
        if (c == y1) l2y1 = l2[c];
    }
    float contrib = r_u * ((lse1 - l1y2) + (lse2 - l2y1));

    int hm = h & 3, wm = w & 3;
    int dn = (b << 14) + ((h >> 2) << 7) + (w >> 2);
    if (((hm==1)||(hm==2)) && ((wm==1)||(wm==2)))
        g_ru4[dn*4 + (hm-1)*2 + (wm-1)] = r_u;
    if (hm == 0 && wm == 0)
        g_pseudo[dn] = (unsigned char)((y1 == y2) ? y1 : 0);

    float v = warpSum(contrib);
    if ((tid & 31) == 0) sred[tid >> 5] = v;
    __syncthreads();
    if (tid == 0){
        float t = 0.f;
#pragma unroll
        for (int k = 0; k < 8; k++) t += sred[k];
        atomicAdd(&g_ucps, (double)t);
    }
}

// ===== kernel U: unlabeled class stats + rare anchored feature sums =========
__global__ __launch_bounds__(256) void kU(const float* __restrict__ fu1,
                                          const float* __restrict__ fu2,
                                          const int* __restrict__ cur,
                                          const int* __restrict__ mxit){
    __shared__ float s_cu[CC], s_w[CC];
    __shared__ float s_tau;
    int tid = threadIdx.x, lane = tid & 31;
    if (tid < CC){ s_cu[tid] = 0.f; s_w[tid] = 0.f; }
    if (tid == 0){
        int mi = *mxit; if (mi < 1) mi = 1;
        double ratio = (double)(*cur) / (double)mi;
        s_tau = (float)(0.85 - 0.35 * cos(1.5707963267948966 * ratio));
    }
    __syncthreads();
    float tau = s_tau;

#pragma unroll
    for (int rep = 0; rep < 2; rep++){
        int n = (blockIdx.x * 512) + rep*256 + tid;
        int lab = (int)g_pseudo[n];
        float4 r4 = *(const float4*)&g_ru4[n*4];
        float r = 0.25f*(r4.x + r4.y + r4.z + r4.w);
        float wgt = (r > tau) ? r : 0.f;
        bool hot = (wgt != 0.f);

        atomicAdd(&s_cu[lab], 1.f);
        if (hot) atomicAdd(&s_w[lab], wgt);

        unsigned act = __ballot_sync(0xffffffffu, hot);
        while (act){
            int p = __ffs(act) - 1; act &= act - 1;
            int labp = __shfl_sync(0xffffffffu, lab, p);
            float wp = __shfl_sync(0xffffffffu, wgt, p);
            int np   = __shfl_sync(0xffffffffu, n, p);
            int b = np >> 14, ij = np & (HWF-1);
            size_t base = (size_t)b*DD*HWF + ij;
#pragma unroll
            for (int k = 0; k < 4; k++){
                int d = k*32 + lane;
                size_t o = base + (size_t)d * HWF;
                float v = 0.5f*(__ldg(&fu1[o]) + __ldg(&fu2[o]));
                atomicAdd(&g_sum_u[labp*DD + d], wp * v);
            }
        }
    }
    __syncthreads();
    if (tid < CC){
        atomicAdd(&g_cnt_u [tid], s_cu[tid]);
        atomicAdd(&g_wsum_u[tid], s_w [tid]);
    }
}

// ===== kernel C: merge + memory update + emit duplicated bank ===============
__global__ void kC(const float* __restrict__ memory,
                   const unsigned char* __restrict__ meminit){
    int c = blockIdx.x, d = threadIdx.x;
    __shared__ float swarp[4];

    float cntl = g_cnt_l[c], cntu = g_cnt_u[c], wsum = g_wsum_u[c];
    bool plp = (cntl >= 1.f), pup = (cntu >= 1.f);
    float pl = g_sum_l[c*DD + d] / (cntl + 1e-7f);
    float pu = g_sum_u[c*DD + d] / (wsum + 1e-7f);
    float merged = (plp && pup) ? (0.7f*pl + 0.3f*pu) : (plp ? pl : pu);

    float v = warpSum(merged * merged);
    if ((d & 31) == 0) swarp[d >> 5] = v;
    __syncthreads();
    float nrm = sqrtf(swarp[0] + swarp[1] + swarp[2] + swarp[3]);
    float pn = merged / fmaxf(nrm, 1e-12f);

    float mv = memory[c*DD + d];
    float ev = 0.999f*mv + 0.001f*pn;
    __syncthreads();
    float v2 = warpSum(ev * ev);
    if ((d & 31) == 0) swarp[d >> 5] = v2;
    __syncthreads();
    float n2 = sqrtf(swarp[0] + swarp[1] + swarp[2] + swarp[3]);
    float ema = ev / fmaxf(n2, 1e-12f);

    bool init = (meminit[c] != 0);
    bool present = plp || pup;
    float newv = present ? (init ? ema : pn) : mv;
    g_mem[c*DD + d] = newv;
    g_memdup[d*20 + c] = fdup(newv);       // [d][c] duplicated-pair layout
    if (d == 0) g_init[c] = (init || present) ? 1 : 0;
}

// ===== kernel D: hard contrastive, 4 px/thread, const+shared split ==========
__global__ __launch_bounds__(128) void kD(const float* __restrict__ fl1,
                                          const float* __restrict__ fl2,
                                          const float* __restrict__ fu1,
                                          const float* __restrict__ fu2,
                                          const int*   __restrict__ gt,
                                          float* __restrict__ out){
    int fid = blockIdx.y;
    const float* f = (fid==0) ? fl1 : (fid==1) ? fl2 : (fid==2) ? fu1 : fu2;

    __shared__ __align__(16) u64 s_bank[DD*10];  // upper half: c2 = 5..9
    __shared__ float sA[4], sB[4];
    __shared__ int s_last;
    for (int t = threadIdx.x; t < DD*10; t += 128){
        int d = t / 10, c2 = t % 10;
        s_bank[t] = g_memdup[d*20 + 10 + c2];    // pairs (10..19) = classes 10..18 + pad
    }
    if (threadIdx.x == 0) s_last = 0;
    __syncthreads();

    int n0 = (blockIdx.x * 128 + threadIdx.x) * 4;
    int b = n0 >> 14;
    const float* fp = f + (size_t)b * DD * HWF + (n0 & (HWF-1));

    u64 acc[2][20];
#pragma unroll
    for (int pr = 0; pr < 2; pr++)
#pragma unroll
        for (int c = 0; c < 20; c++) acc[pr][c] = 0ull;
    u64 nrm2[2] = {0ull, 0ull};

#pragma unroll 4
    for (int d = 0; d < DD; d++){
        ulonglong2 vv = __ldg((const ulonglong2*)(fp + d*HWF));   // 4 px
        u64 va = vv.x, vb = vv.y;
        fma2(nrm2[0], va, va);
        fma2(nrm2[1], vb, vb);
        const ulonglong2* crow = (const ulonglong2*)&c_bank[d*20];     // c2 0..4
        const ulonglong2* srow = (const ulonglong2*)&s_bank[d*10];     // c2 5..9
#pragma unroll
        for (int c2 = 0; c2 < 5; c2++){
            ulonglong2 rv = crow[c2];
            fma2(acc[0][2*c2],   va, rv.x);  fma2(acc[1][2*c2],   vb, rv.x);
            fma2(acc[0][2*c2+1], va, rv.y);  fma2(acc[1][2*c2+1], vb, rv.y);
        }
#pragma unroll
        for (int c2 = 0; c2 < 5; c2++){
            ulonglong2 rv = srow[c2];
            fma2(acc[0][10+2*c2],   va, rv.x);  fma2(acc[1][10+2*c2],   vb, rv.x);
            fma2(acc[0][10+2*c2+1], va, rv.y);  fma2(acc[1][10+2*c2+1], vb, rv.y);
        }
    }

    float blkce = 0.f, blkcv = 0.f;
#pragma unroll
    for (int k = 0; k < 4; k++){
        int n = n0 + k;
        int pr = k >> 1, half = k & 1;
        float nrm = half ? f2hi(nrm2[pr]) : f2lo(nrm2[pr]);
        float inv = 5.0f / fmaxf(sqrtf(nrm), 1e-12f);   // 1/TAU_HARD

        int lab;
        if (fid < 2){
            int j = n & 127, ii = (n >> 7) & 127;
            lab = gt[(size_t)b*HWU + (size_t)(ii*4)*WW + (j*4)];
        } else {
            lab = g_pseudo[n];
        }
        float valid = (float)g_init[lab];

        float mx = -1e30f, acclab = 0.f;
#pragma unroll
        for (int c = 0; c < CC; c++){
            float a = half ? f2hi(acc[pr][c]) : f2lo(acc[pr][c]);
            mx = fmaxf(mx, a);
            if (c == lab) acclab = a;
        }
        float s = 0.f;
#pragma unroll
        for (int c = 0; c < CC; c++){
            float a = half ? f2hi(acc[pr][c]) : f2lo(acc[pr][c]);
            s += __expf((a - mx) * inv);
        }
        float ce = mx*inv + __logf(s) - acclab*inv;
        blkce += ce * valid;
        blkcv += valid;
    }

    float a = warpSum(blkce);
    float bsum = warpSum(blkcv);
    if ((threadIdx.x & 31) == 0){ sA[threadIdx.x >> 5] = a; sB[threadIdx.x >> 5] = bsum; }
    __syncthreads();
    if (threadIdx.x == 0){
        float ta = 0.f, tb = 0.f;
#pragma unroll
        for (int k = 0; k < 4; k++){ ta += sA[k]; tb += sB[k]; }
        atomicAdd(&g_ce[fid], (double)ta);
        atomicAdd(&g_cv[fid], (double)tb);
        __threadfence();
        unsigned done = atomicAdd(&g_done, 1u);
        if (done == KD_BLOCKS - 1) s_last = 1;
    }
    __syncthreads();
    if (s_last && threadIdx.x == 0){
        double h[4];
#pragma unroll
        for (int i = 0; i < 4; i++){
            double nv = g_cv[i];
            h[i] = (nv > 0.0) ? g_ce[i] / fmax(nv, 1.0) : 0.0;
        }
        out[0] = (float)(0.5*(h[0] + h[1]) + 0.5*(h[2] + h[3]));
        out[1] = (float)(g_ucps / (double)NPIX_U);
    }
    __syncthreads();
    if (s_last){   // self-clean scratch for the next graph replay
        for (int t = threadIdx.x; t < CC*DD; t += 128){ g_sum_l[t] = 0.f; g_sum_u[t] = 0.f; }
        if (threadIdx.x < CC){ g_cnt_l[threadIdx.x] = 0.f; g_cnt_u[threadIdx.x] = 0.f; g_wsum_u[threadIdx.x] = 0.f; }
        if (threadIdx.x < 4){ g_ce[threadIdx.x] = 0.0; g_cv[threadIdx.x] = 0.0; }
        if (threadIdx.x == 0){ g_ucps = 0.0; g_done = 0u; }
    }
}

// ---------------- launcher ---------------------------------------------------
extern "C" void kernel_launch(void* const* d_in, const int* in_sizes, int n_in,
                              void* d_out, int out_size){
    const float* fl1 = (const float*)d_in[0];
    const float* fl2 = (const float*)d_in[1];
    const float* fu1 = (const float*)d_in[2];
    const float* fu2 = (const float*)d_in[3];
    // d_in[4], d_in[5] (logits_l1/l2) unused by the reference
    const float* lu1 = (const float*)d_in[6];
    const float* lu2 = (const float*)d_in[7];
    const float* mem = (const float*)d_in[8];
    const int*   gt  = (const int*)d_in[9];
    const unsigned char* meminit = (const unsigned char*)d_in[10];
    const int*   cur = (const int*)d_in[11];
    const int*   mx  = (const int*)d_in[12];

    void *dup_addr = 0, *bank_addr = 0;
    cudaGetSymbolAddress(&dup_addr,  g_memdup);
    cudaGetSymbolAddress(&bank_addr, c_bank);

    kW<<<4608, 256>>>(lu1, lu2, fl1, fl2, gt);
    kU<<<128, 256>>>(fu1, fu2, cur, mx);
    kC<<<CC, 128>>>(mem, meminit);
    cudaMemcpyAsync(bank_addr, dup_addr, sizeof(u64)*DD*20,
                    cudaMemcpyDeviceToDevice, 0);
    kD<<<dim3(NPIX_F/512, 4), 128>>>(fl1, fl2, fu1, fu2, gt, (float*)d_out);
}

// round 10
// speedup vs baseline: 1.0750x; 1.0750x over previous
#include <cuda_runtime.h>
#include <math.h>

#define CC 19
#define DD 128
#define WW 512
#define HWU (512*512)        // 262144
#define HWF (128*128)        // 16384
#define NPIX_F 65536
#define NPIX_U 1048576
#define KD_BLOCKS 512        // (NPIX_F/(128*4))*4 maps

typedef unsigned long long u64;

// ---------------- scratch (device globals; zero at load, self-cleaned) ------
__device__ unsigned char g_pseudo[NPIX_F];
__device__ float         g_sum_l[CC*DD];
__device__ float         g_sum_u[CC*DD];
__device__ float         g_cnt_l[CC];
__device__ float         g_cnt_u[CC];
__device__ float         g_wsum_u[CC];
__device__ float         g_mem[CC*DD];
__device__ __align__(16) u64 g_memdup[DD*20];   // duplicated (m,m) pairs, [d][c]
__device__ int           g_init[CC];
__device__ double        g_ucps;
__device__ double        g_ce[4];
__device__ double        g_cv[4];
__device__ unsigned int  g_done;

// lower half of the bank (c2 = 0..4) via the constant port; upper half via shared.
__constant__ __align__(16) u64 c_bank[DD*20];

__device__ __forceinline__ float warpSum(float v){
#pragma unroll
    for (int o = 16; o; o >>= 1) v += __shfl_down_sync(0xffffffffu, v, o);
    return v;
}
__device__ __forceinline__ void fma2(u64& d, u64 a, u64 b){
    asm("fma.rn.f32x2 %0, %1, %2, %0;" : "+l"(d) : "l"(a), "l"(b));
}
__device__ __forceinline__ float f2lo(u64 x){ return __uint_as_float((unsigned)(x & 0xffffffffu)); }
__device__ __forceinline__ float f2hi(u64 x){ return __uint_as_float((unsigned)(x >> 32)); }
__device__ __forceinline__ u64 fdup(float v){ unsigned u = __float_as_uint(v); return ((u64)u << 32) | u; }

// ===== kernel W: fused [reliability/UCPS + unlabeled stats] + [labeled protos]
// kA blocks cover a 4-row x 64-col strip so each block owns 16 complete
// down-pixels (all 4 bilinear taps + the pseudo-label pixel) -> kU eliminated.
__global__ __launch_bounds__(256) void kW(const float* __restrict__ L1,
                                          const float* __restrict__ L2,
                                          const float* __restrict__ fl1,
                                          const float* __restrict__ fl2,
                                          const float* __restrict__ fu1,
                                          const float* __restrict__ fu2,
                                          const int*   __restrict__ gt,
                                          const int*   __restrict__ cur,
                                          const int*   __restrict__ mxit){
    __shared__ float s_tile[DD*33];
    __shared__ float s_privA[CC*DD];
    __shared__ float s_privB[CC*DD];
    __shared__ float s_cl[CC];
    __shared__ int   s_lab[32];
    __shared__ float sred[8];
    // kA-path extras
    __shared__ float s_ru[16];
    __shared__ int   s_pse[16];
    __shared__ float s_cu[CC], s_wu[CC];
    __shared__ float s_tau;

    int tid = threadIdx.x;
    unsigned bx = blockIdx.x;

    if ((bx % 9u) == 8u){
        // ------------------- labeled prototype block -------------------
        int grp = bx / 9u;                        // 0..511, 4 tiles each
        for (int i = tid; i < CC*DD; i += 256){ s_privA[i] = 0.f; s_privB[i] = 0.f; }
        if (tid < CC) s_cl[tid] = 0.f;
        __syncthreads();

        int px = tid & 31, dgrp = tid >> 5;
        int d  = tid & 127, half = tid >> 7;
        float* priv = half ? s_privB : s_privA;

#pragma unroll 1
        for (int tt = 0; tt < 4; tt++){
            int p0  = (grp*4 + tt) * 32;
            int b   = p0 >> 14;
            int ij0 = p0 & (HWF-1);
            if (tid < 32){
                int ii = (ij0 + tid) >> 7, jj = (ij0 + tid) & 127;
                int lab = gt[(size_t)b*HWU + (size_t)(ii*4)*WW + (jj*4)];
                s_lab[tid] = lab;
                atomicAdd(&s_cl[lab], 1.f);
            }
            const float* b1 = fl1 + (size_t)b*DD*HWF + ij0 + px;
            const float* b2 = fl2 + (size_t)b*DD*HWF + ij0 + px;
#pragma unroll
            for (int k = 0; k < 16; k++){
                int dd = dgrp*16 + k;
                int o = dd*HWF;
                s_tile[dd*33 + px] = 0.5f*(__ldg(b1 + o) + __ldg(b2 + o));
            }
            __syncthreads();
#pragma unroll
            for (int p = 0; p < 16; p++){
                int pp = half*16 + p;
                int lab = s_lab[pp];
                priv[lab*DD + d] += s_tile[d*33 + pp];
            }
            __syncthreads();
        }
        for (int t = tid; t < CC*DD; t += 256)
            atomicAdd(&g_sum_l[t], s_privA[t] + s_privB[t]);
        if (tid < CC) atomicAdd(&g_cnt_l[tid], s_cl[tid]);
        return;
    }

    // --------------------------- kA block (4 rows x 64 cols) ----------
    int aidx = bx - bx/9u;                        // 0..4095
    int b  = aidx >> 10;                          // 4 batches
    int rg = (aidx >> 3) & 127;                   // row-group = down-row i
    int cg = aidx & 7;                            // col-group (64 wide)
    int r4 = tid >> 6;                            // 0..3 row within group
    int col = tid & 63;                           // 0..63
    int h = rg*4 + r4;
    int w = cg*64 + col;

    if (tid < 16) s_ru[tid] = 0.f;
    if (tid < CC){ s_cu[tid] = 0.f; s_wu[tid] = 0.f; }
    if (tid == 0){
        int mi = *mxit; if (mi < 1) mi = 1;
        double ratio = (double)(*cur) / (double)mi;
        s_tau = (float)(0.85 - 0.35 * cos(1.5707963267948966 * ratio));
    }
    __syncthreads();

    const float* p1 = L1 + (size_t)b * CC * HWU + (size_t)h * WW + w;
    const float* p2 = L2 + (size_t)b * CC * HWU + (size_t)h * WW + w;

    float l1[CC], l2[CC], e1[CC], e2[CC];
#pragma unroll
    for (int c = 0; c < CC; c++){
        l1[c] = __ldg(p1 + c*HWU);
        l2[c] = __ldg(p2 + c*HWU);
    }
    float m1 = l1[0], m2 = l2[0];
    int y1 = 0, y2 = 0;
#pragma unroll
    for (int c = 1; c < CC; c++){
        if (l1[c] > m1){ m1 = l1[c]; y1 = c; }
        if (l2[c] > m2){ m2 = l2[c]; y2 = c; }
    }
    float s1 = 0.f, s2 = 0.f;
#pragma unroll
    for (int c = 0; c < CC; c++){
        e1[c] = __expf(l1[c] - m1); s1 += e1[c];
        e2[c] = __expf(l2[c] - m2); s2 += e2[c];
    }
    float lse1 = m1 + __logf(s1), lse2 = m2 + __logf(s2);
    float i1 = __fdividef(1.f, s1), i2 = __fdividef(1.f, s2);

    const float LOGEPS = -16.118095651f;          // log(1e-7)
    float kl = 0.f;
#pragma unroll
    for (int c = 0; c < CC; c++){
        float q1 = e1[c]*i1, q2 = e2[c]*i2;
        float logm = __logf(fmaxf(0.5f*(q1+q2), 1e-7f));
        kl += q1 * (fmaxf(l1[c]-lse1, LOGEPS) - logm)
            + q2 * (fmaxf(l2[c]-lse2, LOGEPS) - logm);
    }
    float conf = 0.5f*(i1 + i2);
    float r_u  = (y1 == y2) ? conf * __expf(-0.5f*kl) : 0.f;

    float l1y2 = 0.f, l2y1 = 0.f;
#pragma unroll
    for (int c = 0; c < CC; c++){
        if (c == y2) l1y2 = l1[c];
        if (c == y1) l2y1 = l2[c];
    }
    float contrib = r_u * ((lse1 - l1y2) + (lse2 - l2y1));

    // taps (rows 1,2; cols 4j+1,4j+2) and pseudo (row 0, col 4j) in-block
    int jj = col >> 2;                            // down-pixel within block
    int cm = col & 3;
    int dn = (b << 14) + (rg << 7) + (cg*16 + jj);
    if ((r4 == 1 || r4 == 2) && (cm == 1 || cm == 2))
        atomicAdd(&s_ru[jj], 0.25f * r_u);
    if (r4 == 0 && cm == 0){
        int ps = (y1 == y2) ? y1 : 0;
        s_pse[jj] = ps;
        g_pseudo[dn] = (unsigned char)ps;
    }
    __syncthreads();

    // first warp: per-down-pixel unlabeled stats + rare anchored sums
    if (tid < 32){
        int lab = 0; float wgt = 0.f; bool hot = false;
        if (tid < 16){
            float r = s_ru[tid];
            lab = s_pse[tid];
            atomicAdd(&s_cu[lab], 1.f);
            if (r > s_tau){ wgt = r; hot = true; atomicAdd(&s_wu[lab], r); }
        }
        unsigned act = __ballot_sync(0xffffffffu, hot);
        while (act){
            int p = __ffs(act) - 1; act &= act - 1;
            int labp = __shfl_sync(0xffffffffu, lab, p);
            float wp = __shfl_sync(0xffffffffu, wgt, p);
            int ij = (rg << 7) + (cg*16 + p);
            size_t base = (size_t)b*DD*HWF + ij;
#pragma unroll
            for (int k = 0; k < 4; k++){
                int d = k*32 + tid;
                size_t o = base + (size_t)d * HWF;
                float v = 0.5f*(__ldg(&fu1[o]) + __ldg(&fu2[o]));
                atomicAdd(&g_sum_u[labp*DD + d], wp * v);
            }
        }
    }

    // UCPS block reduction
    float v = warpSum(contrib);
    if ((tid & 31) == 0) sred[tid >> 5] = v;
    __syncthreads();
    if (tid == 0){
        float t = 0.f;
#pragma unroll
        for (int k = 0; k < 8; k++) t += sred[k];
        atomicAdd(&g_ucps, (double)t);
    }
    if (tid < CC){
        if (s_cu[tid] != 0.f) atomicAdd(&g_cnt_u[tid],  s_cu[tid]);
        if (s_wu[tid] != 0.f) atomicAdd(&g_wsum_u[tid], s_wu[tid]);
    }
}

// ===== kernel C: merge + memory update + emit duplicated bank ===============
__global__ void kC(const float* __restrict__ memory,
                   const unsigned char* __restrict__ meminit){
    int c = blockIdx.x, d = threadIdx.x;
    __shared__ float swarp[4];

    float cntl = g_cnt_l[c], cntu = g_cnt_u[c], wsum = g_wsum_u[c];
    bool plp = (cntl >= 1.f), pup = (cntu >= 1.f);
    float pl = g_sum_l[c*DD + d] / (cntl + 1e-7f);
    float pu = g_sum_u[c*DD + d] / (wsum + 1e-7f);
    float merged = (plp && pup) ? (0.7f*pl + 0.3f*pu) : (plp ? pl : pu);

    float v = warpSum(merged * merged);
    if ((d & 31) == 0) swarp[d >> 5] = v;
    __syncthreads();
    float nrm = sqrtf(swarp[0] + swarp[1] + swarp[2] + swarp[3]);
    float pn = merged / fmaxf(nrm, 1e-12f);

    float mv = memory[c*DD + d];
    float ev = 0.999f*mv + 0.001f*pn;
    __syncthreads();
    float v2 = warpSum(ev * ev);
    if ((d & 31) == 0) swarp[d >> 5] = v2;
    __syncthreads();
    float n2 = sqrtf(swarp[0] + swarp[1] + swarp[2] + swarp[3]);
    float ema = ev / fmaxf(n2, 1e-12f);

    bool init = (meminit[c] != 0);
    bool present = plp || pup;
    float newv = present ? (init ? ema : pn) : mv;
    g_mem[c*DD + d] = newv;
    g_memdup[d*20 + c] = fdup(newv);       // [d][c] duplicated-pair layout
    if (d == 0) g_init[c] = (init || present) ? 1 : 0;
}

// ===== kernel D: hard contrastive, 4 px/thread, const+shared split ==========
__global__ __launch_bounds__(128) void kD(const float* __restrict__ fl1,
                                          const float* __restrict__ fl2,
                                          const float* __restrict__ fu1,
                                          const float* __restrict__ fu2,
                                          const int*   __restrict__ gt,
                                          float* __restrict__ out){
    int fid = blockIdx.y;
    const float* f = (fid==0) ? fl1 : (fid==1) ? fl2 : (fid==2) ? fu1 : fu2;

    __shared__ __align__(16) u64 s_bank[DD*10];  // upper half: c2 = 5..9
    __shared__ float sA[4], sB[4];
    __shared__ int s_last;
    for (int t = threadIdx.x; t < DD*10; t += 128){
        int d = t / 10, c2 = t % 10;
        s_bank[t] = g_memdup[d*20 + 10 + c2];    // pairs (10..19) = classes 10..18 + pad
    }
    if (threadIdx.x == 0) s_last = 0;
    __syncthreads();

    int n0 = (blockIdx.x * 128 + threadIdx.x) * 4;
    int b = n0 >> 14;
    const float* fp = f + (size_t)b * DD * HWF + (n0 & (HWF-1));

    u64 acc[2][20];
#pragma unroll
    for (int pr = 0; pr < 2; pr++)
#pragma unroll
        for (int c = 0; c < 20; c++) acc[pr][c] = 0ull;
    u64 nrm2[2] = {0ull, 0ull};

#pragma unroll 4
    for (int d = 0; d < DD; d++){
        ulonglong2 vv = __ldg((const ulonglong2*)(fp + d*HWF));   // 4 px
        u64 va = vv.x, vb = vv.y;
        fma2(nrm2[0], va, va);
        fma2(nrm2[1], vb, vb);
        const ulonglong2* crow = (const ulonglong2*)&c_bank[d*20];     // c2 0..4
        const ulonglong2* srow = (const ulonglong2*)&s_bank[d*10];     // c2 5..9
#pragma unroll
        for (int c2 = 0; c2 < 5; c2++){
            ulonglong2 rv = crow[c2];
            fma2(acc[0][2*c2],   va, rv.x);  fma2(acc[1][2*c2],   vb, rv.x);
            fma2(acc[0][2*c2+1], va, rv.y);  fma2(acc[1][2*c2+1], vb, rv.y);
        }
#pragma unroll
        for (int c2 = 0; c2 < 5; c2++){
            ulonglong2 rv = srow[c2];
            fma2(acc[0][10+2*c2],   va, rv.x);  fma2(acc[1][10+2*c2],   vb, rv.x);
            fma2(acc[0][10+2*c2+1], va, rv.y);  fma2(acc[1][10+2*c2+1], vb, rv.y);
        }
    }

    float blkce = 0.f, blkcv = 0.f;
#pragma unroll
    for (int k = 0; k < 4; k++){
        int n = n0 + k;
        int pr = k >> 1, half = k & 1;
        float nrm = half ? f2hi(nrm2[pr]) : f2lo(nrm2[pr]);
        float inv = 5.0f / fmaxf(sqrtf(nrm), 1e-12f);   // 1/TAU_HARD

        int lab;
        if (fid < 2){
            int j = n & 127, ii = (n >> 7) & 127;
            lab = gt[(size_t)b*HWU + (size_t)(ii*4)*WW + (j*4)];
        } else {
            lab = g_pseudo[n];
        }
        float valid = (float)g_init[lab];

        float mx = -1e30f, acclab = 0.f;
#pragma unroll
        for (int c = 0; c < CC; c++){
            float a = half ? f2hi(acc[pr][c]) : f2lo(acc[pr][c]);
            mx = fmaxf(mx, a);
            if (c == lab) acclab = a;
        }
        float s = 0.f;
#pragma unroll
        for (int c = 0; c < CC; c++){
            float a = half ? f2hi(acc[pr][c]) : f2lo(acc[pr][c]);
            s += __expf((a - mx) * inv);
        }
        float ce = mx*inv + __logf(s) - acclab*inv;
        blkce += ce * valid;
        blkcv += valid;
    }

    float a = warpSum(blkce);
    float bsum = warpSum(blkcv);
    if ((threadIdx.x & 31) == 0){ sA[threadIdx.x >> 5] = a; sB[threadIdx.x >> 5] = bsum; }
    __syncthreads();
    if (threadIdx.x == 0){
        float ta = 0.f, tb = 0.f;
#pragma unroll
        for (int k = 0; k < 4; k++){ ta += sA[k]; tb += sB[k]; }
        atomicAdd(&g_ce[fid], (double)ta);
        atomicAdd(&g_cv[fid], (double)tb);
        __threadfence();
        unsigned done = atomicAdd(&g_done, 1u);
        if (done == KD_BLOCKS - 1) s_last = 1;
    }
    __syncthreads();
    if (s_last && threadIdx.x == 0){
        double h[4];
#pragma unroll
        for (int i = 0; i < 4; i++){
            double nv = g_cv[i];
            h[i] = (nv > 0.0) ? g_ce[i] / fmax(nv, 1.0) : 0.0;
        }
        out[0] = (float)(0.5*(h[0] + h[1]) + 0.5*(h[2] + h[3]));
        out[1] = (float)(g_ucps / (double)NPIX_U);
    }
    __syncthreads();
    if (s_last){   // self-clean scratch for the next graph replay
        for (int t = threadIdx.x; t < CC*DD; t += 128){ g_sum_l[t] = 0.f; g_sum_u[t] = 0.f; }
        if (threadIdx.x < CC){ g_cnt_l[threadIdx.x] = 0.f; g_cnt_u[threadIdx.x] = 0.f; g_wsum_u[threadIdx.x] = 0.f; }
        if (threadIdx.x < 4){ g_ce[threadIdx.x] = 0.0; g_cv[threadIdx.x] = 0.0; }
        if (threadIdx.x == 0){ g_ucps = 0.0; g_done = 0u; }
    }
}

// ---------------- launcher ---------------------------------------------------
extern "C" void kernel_launch(void* const* d_in, const int* in_sizes, int n_in,
                              void* d_out, int out_size){
    const float* fl1 = (const float*)d_in[0];
    const float* fl2 = (const float*)d_in[1];
    const float* fu1 = (const float*)d_in[2];
    const float* fu2 = (const float*)d_in[3];
    // d_in[4], d_in[5] (logits_l1/l2) unused by the reference
    const float* lu1 = (const float*)d_in[6];
    const float* lu2 = (const float*)d_in[7];
    const float* mem = (const float*)d_in[8];
    const int*   gt  = (const int*)d_in[9];
    const unsigned char* meminit = (const unsigned char*)d_in[10];
    const int*   cur = (const int*)d_in[11];
    const int*   mx  = (const int*)d_in[12];

    void *dup_addr = 0, *bank_addr = 0;
    cudaGetSymbolAddress(&dup_addr,  g_memdup);
    cudaGetSymbolAddress(&bank_addr, c_bank);

    kW<<<4608, 256>>>(lu1, lu2, fl1, fl2, fu1, fu2, gt, cur, mx);
    kC<<<CC, 128>>>(mem, meminit);
    cudaMemcpyAsync(bank_addr, dup_addr, sizeof(u64)*DD*20,
                    cudaMemcpyDeviceToDevice, 0);
    kD<<<dim3(NPIX_F/512, 4), 128>>>(fl1, fl2, fu1, fu2, gt, (float*)d_out);
}

// round 11
// speedup vs baseline: 1.1557x; 1.0751x over previous
#include <cuda_runtime.h>
#include <math.h>

#define CC 19
#define DD 128
#define WW 512
#define HWU (512*512)        // 262144
#define HWF (128*128)        // 16384
#define NPIX_F 65536
#define NPIX_U 1048576
#define KD_BLOCKS 512        // (NPIX_F/(128*4))*4 maps

typedef unsigned long long u64;

// ---------------- scratch (device globals; zero at load, self-cleaned) ------
__device__ __align__(16) float g_ru4[NPIX_F*4];
__device__ unsigned char g_pseudo[NPIX_F];
__device__ float         g_sum_l[CC*DD];
__device__ float         g_sum_u[CC*DD];
__device__ float         g_cnt_l[CC];
__device__ float         g_cnt_u[CC];
__device__ float         g_wsum_u[CC];
__device__ float         g_mem[CC*DD];
__device__ __align__(16) u64 g_memdup[DD*20];   // duplicated (m,m) pairs, [d][c]
__device__ int           g_init[CC];
__device__ double        g_ucps;
__device__ double        g_ce[4];
__device__ double        g_cv[4];
__device__ unsigned int  g_done;

// lower half of the bank (c2 = 0..4) via the constant port; upper half via shared.
__constant__ __align__(16) u64 c_bank[DD*20];

__device__ __forceinline__ float warpSum(float v){
#pragma unroll
    for (int o = 16; o; o >>= 1) v += __shfl_down_sync(0xffffffffu, v, o);
    return v;
}
__device__ __forceinline__ void fma2(u64& d, u64 a, u64 b){
    asm("fma.rn.f32x2 %0, %1, %2, %0;" : "+l"(d) : "l"(a), "l"(b));
}
__device__ __forceinline__ float f2lo(u64 x){ return __uint_as_float((unsigned)(x & 0xffffffffu)); }
__device__ __forceinline__ float f2hi(u64 x){ return __uint_as_float((unsigned)(x >> 32)); }
__device__ __forceinline__ u64 fdup(float v){ unsigned u = __float_as_uint(v); return ((u64)u << 32) | u; }

// ===== kernel W: fused [reliability/UCPS]  +  [labeled prototype sums] ======
__global__ __launch_bounds__(256) void kW(const float* __restrict__ L1,
                                          const float* __restrict__ L2,
                                          const float* __restrict__ fl1,
                                          const float* __restrict__ fl2,
                                          const int*   __restrict__ gt){
    __shared__ float s_tile[DD*33];
    __shared__ float s_privA[CC*DD];
    __shared__ float s_privB[CC*DD];
    __shared__ float s_cl[CC];
    __shared__ int   s_lab[32];
    __shared__ float sred[8];

    int tid = threadIdx.x;
    unsigned bx = blockIdx.x;

    if ((bx % 9u) == 8u){
        // ------------------- labeled prototype block -------------------
        int grp = bx / 9u;                        // 0..511, 4 tiles each
        for (int i = tid; i < CC*DD; i += 256){ s_privA[i] = 0.f; s_privB[i] = 0.f; }
        if (tid < CC) s_cl[tid] = 0.f;
        __syncthreads();

        int px = tid & 31, dgrp = tid >> 5;
        int d  = tid & 127, half = tid >> 7;
        float* priv = half ? s_privB : s_privA;

#pragma unroll 1
        for (int tt = 0; tt < 4; tt++){
            int p0  = (grp*4 + tt) * 32;
            int b   = p0 >> 14;
            int ij0 = p0 & (HWF-1);
            if (tid < 32){
                int ii = (ij0 + tid) >> 7, jj = (ij0 + tid) & 127;
                int lab = gt[(size_t)b*HWU + (size_t)(ii*4)*WW + (jj*4)];
                s_lab[tid] = lab;
                atomicAdd(&s_cl[lab], 1.f);
            }
            const float* b1 = fl1 + (size_t)b*DD*HWF + ij0 + px;
            const float* b2 = fl2 + (size_t)b*DD*HWF + ij0 + px;
#pragma unroll
            for (int k = 0; k < 16; k++){
                int dd = dgrp*16 + k;
                int o = dd*HWF;
                s_tile[dd*33 + px] = 0.5f*(__ldg(b1 + o) + __ldg(b2 + o));
            }
            __syncthreads();
#pragma unroll
            for (int p = 0; p < 16; p++){
                int pp = half*16 + p;
                int lab = s_lab[pp];
                priv[lab*DD + d] += s_tile[d*33 + pp];
            }
            __syncthreads();
        }
        for (int t = tid; t < CC*DD; t += 256)
            atomicAdd(&g_sum_l[t], s_privA[t] + s_privB[t]);
        if (tid < CC) atomicAdd(&g_cnt_l[tid], s_cl[tid]);
        return;
    }

    // --------------------------- kA block -----------------------------
    int aidx = bx - bx/9u;                        // 0..4095
    int idx = aidx*256 + tid;
    int w = idx & (WW-1);
    int h = (idx >> 9) & 511;
    int b = idx >> 18;
    const float* p1 = L1 + (size_t)b * CC * HWU + (size_t)h * WW + w;
    const float* p2 = L2 + (size_t)b * CC * HWU + (size_t)h * WW + w;

    float l1[CC], l2[CC], e1[CC], e2[CC];
#pragma unroll
    for (int c = 0; c < CC; c++){
        l1[c] = __ldcs(p1 + c*HWU);               // streaming: don't evict feats
        l2[c] = __ldcs(p2 + c*HWU);
    }
    float m1 = l1[0], m2 = l2[0];
    int y1 = 0, y2 = 0;
#pragma unroll
    for (int c = 1; c < CC; c++){
        if (l1[c] > m1){ m1 = l1[c]; y1 = c; }
        if (l2[c] > m2){ m2 = l2[c]; y2 = c; }
    }
    float s1 = 0.f, s2 = 0.f;
#pragma unroll
    for (int c = 0; c < CC; c++){
        e1[c] = __expf(l1[c] - m1); s1 += e1[c];
        e2[c] = __expf(l2[c] - m2); s2 += e2[c];
    }
    float lse1 = m1 + __logf(s1), lse2 = m2 + __logf(s2);
    float i1 = __fdividef(1.f, s1), i2 = __fdividef(1.f, s2);

    const float LOGEPS = -16.118095651f;          // log(1e-7)
    float kl = 0.f;
#pragma unroll
    for (int c = 0; c < CC; c++){
        float q1 = e1[c]*i1, q2 = e2[c]*i2;
        float logm = __logf(fmaxf(0.5f*(q1+q2), 1e-7f));
        kl += q1 * (fmaxf(l1[c]-lse1, LOGEPS) - logm)
            + q2 * (fmaxf(l2[c]-lse2, LOGEPS) - logm);
    }
    float conf = 0.5f*(i1 + i2);
    float r_u  = (y1 == y2) ? conf * __expf(-0.5f*kl) : 0.f;

    float l1y2 = 0.f, l2y1 = 0.f;
#pragma unroll
    for (int c = 0; c < CC; c++){
        if (c == y2) l1y2 = l1[c];
        if (c == y1) l2y1 = l2[c];
    }
    float contrib = r_u * ((lse1 - l1y2) + (lse2 - l2y1));

    int hm = h & 3, wm = w & 3;
    int dn = (b << 14) + ((h >> 2) << 7) + (w >> 2);
    if (((hm==1)||(hm==2)) && ((wm==1)||(wm==2)))
        g_ru4[dn*4 + (hm-1)*2 + (wm-1)] = r_u;
    if (hm == 0 && wm == 0)
        g_pseudo[dn] = (unsigned char)((y1 == y2) ? y1 : 0);

    float v = warpSum(contrib);
    if ((tid & 31) == 0) sred[tid >> 5] = v;
    __syncthreads();
    if (tid == 0){
        float t = 0.f;
#pragma unroll
        for (int k = 0; k < 8; k++) t += sred[k];
        atomicAdd(&g_ucps, (double)t);
    }
}

// ===== kernel U: unlabeled class stats + rare anchored feature sums =========
__global__ __launch_bounds__(256) void kU(const float* __restrict__ fu1,
                                          const float* __restrict__ fu2,
                                          const int* __restrict__ cur,
                                          const int* __restrict__ mxit){
    __shared__ float s_cu[CC], s_w[CC];
    __shared__ float s_tau;
    int tid = threadIdx.x, lane = tid & 31;
    if (tid < CC){ s_cu[tid] = 0.f; s_w[tid] = 0.f; }
    if (tid == 0){
        int mi = *mxit; if (mi < 1) mi = 1;
        double ratio = (double)(*cur) / (double)mi;
        s_tau = (float)(0.85 - 0.35 * cos(1.5707963267948966 * ratio));
    }
    __syncthreads();
    float tau = s_tau;

#pragma unroll
    for (int rep = 0; rep < 2; rep++){
        int n = (blockIdx.x * 512) + rep*256 + tid;
        int lab = (int)g_pseudo[n];
        float4 r4 = *(const float4*)&g_ru4[n*4];
        float r = 0.25f*(r4.x + r4.y + r4.z + r4.w);
        float wgt = (r > tau) ? r : 0.f;
        bool hot = (wgt != 0.f);

        atomicAdd(&s_cu[lab], 1.f);
        if (hot) atomicAdd(&s_w[lab], wgt);

        unsigned act = __ballot_sync(0xffffffffu, hot);
        while (act){
            int p = __ffs(act) - 1; act &= act - 1;
            int labp = __shfl_sync(0xffffffffu, lab, p);
            float wp = __shfl_sync(0xffffffffu, wgt, p);
            int np   = __shfl_sync(0xffffffffu, n, p);
            int b = np >> 14, ij = np & (HWF-1);
            size_t base = (size_t)b*DD*HWF + ij;
#pragma unroll
            for (int k = 0; k < 4; k++){
                int d = k*32 + lane;
                size_t o = base + (size_t)d * HWF;
                float v = 0.5f*(__ldg(&fu1[o]) + __ldg(&fu2[o]));
                atomicAdd(&g_sum_u[labp*DD + d], wp * v);
            }
        }
    }
    __syncthreads();
    if (tid < CC){
        atomicAdd(&g_cnt_u [tid], s_cu[tid]);
        atomicAdd(&g_wsum_u[tid], s_w [tid]);
    }
}

// ===== kernel C: merge + memory update + emit duplicated bank ===============
__global__ void kC(const float* __restrict__ memory,
                   const unsigned char* __restrict__ meminit){
    int c = blockIdx.x, d = threadIdx.x;
    __shared__ float swarp[4];

    float cntl = g_cnt_l[c], cntu = g_cnt_u[c], wsum = g_wsum_u[c];
    bool plp = (cntl >= 1.f), pup = (cntu >= 1.f);
    float pl = g_sum_l[c*DD + d] / (cntl + 1e-7f);
    float pu = g_sum_u[c*DD + d] / (wsum + 1e-7f);
    float merged = (plp && pup) ? (0.7f*pl + 0.3f*pu) : (plp ? pl : pu);

    float v = warpSum(merged * merged);
    if ((d & 31) == 0) swarp[d >> 5] = v;
    __syncthreads();
    float nrm = sqrtf(swarp[0] + swarp[1] + swarp[2] + swarp[3]);
    float pn = merged / fmaxf(nrm, 1e-12f);

    float mv = memory[c*DD + d];
    float ev = 0.999f*mv + 0.001f*pn;
    __syncthreads();
    float v2 = warpSum(ev * ev);
    if ((d & 31) == 0) swarp[d >> 5] = v2;
    __syncthreads();
    float n2 = sqrtf(swarp[0] + swarp[1] + swarp[2] + swarp[3]);
    float ema = ev / fmaxf(n2, 1e-12f);

    bool init = (meminit[c] != 0);
    bool present = plp || pup;
    float newv = present ? (init ? ema : pn) : mv;
    g_mem[c*DD + d] = newv;
    g_memdup[d*20 + c] = fdup(newv);       // [d][c] duplicated-pair layout
    if (d == 0) g_init[c] = (init || present) ? 1 : 0;
}

// ===== kernel D: hard contrastive, 4 px/thread, const+shared split ==========
__global__ __launch_bounds__(128) void kD(const float* __restrict__ fl1,
                                          const float* __restrict__ fl2,
                                          const float* __restrict__ fu1,
                                          const float* __restrict__ fu2,
                                          const int*   __restrict__ gt,
                                          float* __restrict__ out){
    int fid = blockIdx.y;
    const float* f = (fid==0) ? fl1 : (fid==1) ? fl2 : (fid==2) ? fu1 : fu2;

    __shared__ __align__(16) u64 s_bank[DD*10];  // upper half: c2 = 5..9
    __shared__ float sA[4], sB[4];
    __shared__ int s_last;
    for (int t = threadIdx.x; t < DD*10; t += 128){
        int d = t / 10, c2 = t % 10;
        s_bank[t] = g_memdup[d*20 + 10 + c2];    // pairs (10..19) = classes 10..18 + pad
    }
    if (threadIdx.x == 0) s_last = 0;
    __syncthreads();

    int n0 = (blockIdx.x * 128 + threadIdx.x) * 4;
    int b = n0 >> 14;
    const float* fp = f + (size_t)b * DD * HWF + (n0 & (HWF-1));

    u64 acc[2][20];
#pragma unroll
    for (int pr = 0; pr < 2; pr++)
#pragma unroll
        for (int c = 0; c < 20; c++) acc[pr][c] = 0ull;
    u64 nrm2[2] = {0ull, 0ull};

#pragma unroll 8
    for (int d = 0; d < DD; d++){
        ulonglong2 vv = __ldg((const ulonglong2*)(fp + d*HWF));   // 4 px
        u64 va = vv.x, vb = vv.y;
        fma2(nrm2[0], va, va);
        fma2(nrm2[1], vb, vb);
        const ulonglong2* crow = (const ulonglong2*)&c_bank[d*20];     // c2 0..4
        const ulonglong2* srow = (const ulonglong2*)&s_bank[d*10];     // c2 5..9
#pragma unroll
        for (int c2 = 0; c2 < 5; c2++){
            ulonglong2 rv = crow[c2];
            fma2(acc[0][2*c2],   va, rv.x);  fma2(acc[1][2*c2],   vb, rv.x);
            fma2(acc[0][2*c2+1], va, rv.y);  fma2(acc[1][2*c2+1], vb, rv.y);
        }
#pragma unroll
        for (int c2 = 0; c2 < 5; c2++){
            ulonglong2 rv = srow[c2];
            fma2(acc[0][10+2*c2],   va, rv.x);  fma2(acc[1][10+2*c2],   vb, rv.x);
            fma2(acc[0][10+2*c2+1], va, rv.y);  fma2(acc[1][10+2*c2+1], vb, rv.y);
        }
    }

    float blkce = 0.f, blkcv = 0.f;
#pragma unroll
    for (int k = 0; k < 4; k++){
        int n = n0 + k;
        int pr = k >> 1, half = k & 1;
        float nrm = half ? f2hi(nrm2[pr]) : f2lo(nrm2[pr]);
        float inv = 5.0f / fmaxf(sqrtf(nrm), 1e-12f);   // 1/TAU_HARD

        int lab;
        if (fid < 2){
            int j = n & 127, ii = (n >> 7) & 127;
            lab = gt[(size_t)b*HWU + (size_t)(ii*4)*WW + (j*4)];
        } else {
            lab = g_pseudo[n];
        }
        float valid = (float)g_init[lab];

        float mx = -1e30f, acclab = 0.f;
#pragma unroll
        for (int c = 0; c < CC; c++){
            float a = half ? f2hi(acc[pr][c]) : f2lo(acc[pr][c]);
            mx = fmaxf(mx, a);
            if (c == lab) acclab = a;
        }
        float s = 0.f;
#pragma unroll
        for (int c = 0; c < CC; c++){
            float a = half ? f2hi(acc[pr][c]) : f2lo(acc[pr][c]);
            s += __expf((a - mx) * inv);
        }
        float ce = mx*inv + __logf(s) - acclab*inv;
        blkce += ce * valid;
        blkcv += valid;
    }

    float a = warpSum(blkce);
    float bsum = warpSum(blkcv);
    if ((threadIdx.x & 31) == 0){ sA[threadIdx.x >> 5] = a; sB[threadIdx.x >> 5] = bsum; }
    __syncthreads();
    if (threadIdx.x == 0){
        float ta = 0.f, tb = 0.f;
#pragma unroll
        for (int k = 0; k < 4; k++){ ta += sA[k]; tb += sB[k]; }
        atomicAdd(&g_ce[fid], (double)ta);
        atomicAdd(&g_cv[fid], (double)tb);
        __threadfence();
        unsigned done = atomicAdd(&g_done, 1u);
        if (done == KD_BLOCKS - 1) s_last = 1;
    }
    __syncthreads();
    if (s_last && threadIdx.x == 0){
        double h[4];
#pragma unroll
        for (int i = 0; i < 4; i++){
            double nv = g_cv[i];
            h[i] = (nv > 0.0) ? g_ce[i] / fmax(nv, 1.0) : 0.0;
        }
        out[0] = (float)(0.5*(h[0] + h[1]) + 0.5*(h[2] + h[3]));
        out[1] = (float)(g_ucps / (double)NPIX_U);
    }
    __syncthreads();
    if (s_last){   // self-clean scratch for the next graph replay
        for (int t = threadIdx.x; t < CC*DD; t += 128){ g_sum_l[t] = 0.f; g_sum_u[t] = 0.f; }
        if (threadIdx.x < CC){ g_cnt_l[threadIdx.x] = 0.f; g_cnt_u[threadIdx.x] = 0.f; g_wsum_u[threadIdx.x] = 0.f; }
        if (threadIdx.x < 4){ g_ce[threadIdx.x] = 0.0; g_cv[threadIdx.x] = 0.0; }
        if (threadIdx.x == 0){ g_ucps = 0.0; g_done = 0u; }
    }
}

// ---------------- launcher ---------------------------------------------------
extern "C" void kernel_launch(void* const* d_in, const int* in_sizes, int n_in,
                              void* d_out, int out_size){
    const float* fl1 = (const float*)d_in[0];
    const float* fl2 = (const float*)d_in[1];
    const float* fu1 = (const float*)d_in[2];
    const float* fu2 = (const float*)d_in[3];
    // d_in[4], d_in[5] (logits_l1/l2) unused by the reference
    const float* lu1 = (const float*)d_in[6];
    const float* lu2 = (const float*)d_in[7];
    const float* mem = (const float*)d_in[8];
    const int*   gt  = (const int*)d_in[9];
    const unsigned char* meminit = (const unsigned char*)d_in[10];
    const int*   cur = (const int*)d_in[11];
    const int*   mx  = (const int*)d_in[12];

    void *dup_addr = 0, *bank_addr = 0;
    cudaGetSymbolAddress(&dup_addr,  g_memdup);
    cudaGetSymbolAddress(&bank_addr, c_bank);

    kW<<<4608, 256>>>(lu1, lu2, fl1, fl2, gt);
    kU<<<128, 256>>>(fu1, fu2, cur, mx);
    kC<<<CC, 128>>>(mem, meminit);
    cudaMemcpyAsync(bank_addr, dup_addr, sizeof(u64)*DD*20,
                    cudaMemcpyDeviceToDevice, 0);
    kD<<<dim3(NPIX_F/512, 4), 128>>>(fl1, fl2, fu1, fu2, gt, (float*)d_out);
}